// round 3
// baseline (speedup 1.0000x reference)
#include <cuda_runtime.h>
#include <cuda_fp16.h>
#include <cuda_bf16.h>
#include <cstdint>

#define N_NODES   100000
#define N_EDGES   1600000
#define IN_FEATS  64
#define OUT_FEATS 64
#define DIM       3
#define N_KERNELS 4
#define KH        (N_KERNELS * OUT_FEATS)   // 256

#define SCAN_BLOCK 512
#define NBLK_SCAN  ((N_NODES + SCAN_BLOCK - 1) / SCAN_BLOCK)   // 196

// ---- scratch (allocation-free rule: __device__ globals) ----
__device__ __half  g_h[(size_t)N_NODES * KH];     // node projections, fp16 (51 MB)
__device__ int     g_count[N_NODES];              // in-degree histogram
__device__ int     g_offsets[N_NODES + 1];        // CSR offsets (by dst)
__device__ int     g_cursor[N_NODES];             // fill cursors
__device__ int     g_bsum[NBLK_SCAN];             // scan block sums
__device__ int     g_rsrc[N_EDGES];               // per-slot: src node
__device__ float4  g_rg[N_EDGES];                 // per-slot: 4 gaussian weights

// ---------------------------------------------------------------------------
// Zero the histogram
// ---------------------------------------------------------------------------
__global__ void zero_count_kernel() {
    int i = blockIdx.x * blockDim.x + threadIdx.x;
    if (i < N_NODES) g_count[i] = 0;
}

// ---------------------------------------------------------------------------
// Histogram of dst
// ---------------------------------------------------------------------------
__global__ void hist_kernel(const int* __restrict__ dst) {
    int e = blockIdx.x * blockDim.x + threadIdx.x;
    if (e < N_EDGES) atomicAdd(&g_count[dst[e]], 1);
}

// ---------------------------------------------------------------------------
// Two-level exclusive scan over g_count -> g_offsets (+ cursor copy)
// ---------------------------------------------------------------------------
__global__ __launch_bounds__(SCAN_BLOCK) void scan1_kernel() {
    __shared__ int tmp[SCAN_BLOCK];
    int t = threadIdx.x;
    int i = blockIdx.x * SCAN_BLOCK + t;
    int x = (i < N_NODES) ? g_count[i] : 0;
    tmp[t] = x;
    __syncthreads();
#pragma unroll
    for (int off = 1; off < SCAN_BLOCK; off <<= 1) {
        int v = (t >= off) ? tmp[t - off] : 0;
        __syncthreads();
        tmp[t] += v;
        __syncthreads();
    }
    if (i < N_NODES) g_offsets[i] = tmp[t] - x;          // exclusive, local
    if (t == SCAN_BLOCK - 1) g_bsum[blockIdx.x] = tmp[t]; // block total
}

__global__ __launch_bounds__(256) void scan2_kernel() {
    __shared__ int tmp[256];
    int t = threadIdx.x;
    int x = (t < NBLK_SCAN) ? g_bsum[t] : 0;
    tmp[t] = x;
    __syncthreads();
#pragma unroll
    for (int off = 1; off < 256; off <<= 1) {
        int v = (t >= off) ? tmp[t - off] : 0;
        __syncthreads();
        tmp[t] += v;
        __syncthreads();
    }
    if (t < NBLK_SCAN) g_bsum[t] = tmp[t] - x;           // exclusive block base
}

__global__ __launch_bounds__(SCAN_BLOCK) void scan3_kernel() {
    int i = blockIdx.x * SCAN_BLOCK + threadIdx.x;
    if (i < N_NODES) {
        int v = g_offsets[i] + g_bsum[blockIdx.x];
        g_offsets[i] = v;
        g_cursor[i]  = v;
    }
    if (i == 0) g_offsets[N_NODES] = N_EDGES;
}

// ---------------------------------------------------------------------------
// Binning: per edge compute 4 gaussian weights, drop {src, g0..g3} into dst bin
// ---------------------------------------------------------------------------
__global__ __launch_bounds__(256) void bin_kernel(const float* __restrict__ pseudo,
                                                  const int*   __restrict__ src,
                                                  const int*   __restrict__ dst,
                                                  const float* __restrict__ mu,
                                                  const float* __restrict__ inv_sigma) {
    int e = blockIdx.x * blockDim.x + threadIdx.x;
    if (e >= N_EDGES) return;

    float px = __ldg(pseudo + 3*e + 0);
    float py = __ldg(pseudo + 3*e + 1);
    float pz = __ldg(pseudo + 3*e + 2);

    float4 g;
    float* gp = &g.x;
#pragma unroll
    for (int k = 0; k < N_KERNELS; k++) {
        float d0 = px - __ldg(mu + k*3 + 0);
        float d1 = py - __ldg(mu + k*3 + 1);
        float d2 = pz - __ldg(mu + k*3 + 2);
        float s0 = __ldg(inv_sigma + k*3 + 0);
        float s1 = __ldg(inv_sigma + k*3 + 1);
        float s2 = __ldg(inv_sigma + k*3 + 2);
        float acc = d0*d0*s0*s0 + d1*d1*s1*s1 + d2*d2*s2*s2;
        gp[k] = __expf(-0.5f * acc);
    }

    int d = __ldg(dst + e);
    int pos = atomicAdd(&g_cursor[d], 1);
    g_rsrc[pos] = __ldg(src + e);
    g_rg[pos]   = g;
}

// ---------------------------------------------------------------------------
// Projection: h[v, o] = sum_j feat[v,j] * W_fc[o,j]  -> fp16
// ---------------------------------------------------------------------------
#define PROJ_TILE 32

__global__ __launch_bounds__(256) void proj_kernel(const float* __restrict__ feat,
                                                   const float* __restrict__ W_fc) {
    __shared__ float sf[PROJ_TILE][IN_FEATS];

    const int o = threadIdx.x;
    const int node0 = blockIdx.x * PROJ_TILE;

    float w[IN_FEATS];
    const float4* wp = reinterpret_cast<const float4*>(W_fc + (size_t)o * IN_FEATS);
#pragma unroll
    for (int q = 0; q < IN_FEATS / 4; q++) {
        float4 v = wp[q];
        w[4*q+0] = v.x; w[4*q+1] = v.y; w[4*q+2] = v.z; w[4*q+3] = v.w;
    }

    const float4* fp = reinterpret_cast<const float4*>(feat + (size_t)node0 * IN_FEATS);
#pragma unroll
    for (int q = 0; q < 2; q++) {
        int idx = threadIdx.x + q * 256;
        float4 v = fp[idx];
        int n = idx >> 4;
        int c = (idx & 15) * 4;
        sf[n][c+0] = v.x; sf[n][c+1] = v.y; sf[n][c+2] = v.z; sf[n][c+3] = v.w;
    }
    __syncthreads();

#pragma unroll 4
    for (int n = 0; n < PROJ_TILE; n++) {
        float acc = 0.f;
#pragma unroll
        for (int j = 0; j < IN_FEATS; j++)
            acc = fmaf(w[j], sf[n][j], acc);
        g_h[(size_t)(node0 + n) * KH + o] = __float2half_rn(acc);
    }
}

// ---------------------------------------------------------------------------
// Aggregation: one warp per node. Lane owns 2 output channels.
// out[v] = feat[v] + bias + sum_{slots of v} sum_k g[k] * h[src, k, :]
// ---------------------------------------------------------------------------
#define AGG_WARPS 8

__global__ __launch_bounds__(AGG_WARPS * 32) void agg_kernel(const float* __restrict__ feat,
                                                             const float* __restrict__ bias,
                                                             float* __restrict__ out) {
    const int warp = threadIdx.x >> 5;
    const int lane = threadIdx.x & 31;
    const int v = blockIdx.x * AGG_WARPS + warp;
    if (v >= N_NODES) return;

    const int beg = g_offsets[v];
    const int end = g_offsets[v + 1];

    float2 acc = *reinterpret_cast<const float2*>(feat + (size_t)v * OUT_FEATS + lane * 2);
    float2 b   = *reinterpret_cast<const float2*>(bias + lane * 2);
    acc.x += b.x; acc.y += b.y;

    int i = beg;
    // 2-way unrolled main loop for MLP across independent edges
    for (; i + 2 <= end; i += 2) {
#pragma unroll
        for (int u = 0; u < 2; u++) {
            int    s = __ldg(g_rsrc + i + u);            // broadcast
            float4 g = __ldg(g_rg   + i + u);            // broadcast
            const __half2* hp = reinterpret_cast<const __half2*>(g_h + (size_t)s * KH);
            float2 f0 = __half22float2(__ldg(hp + 0*32 + lane));
            float2 f1 = __half22float2(__ldg(hp + 1*32 + lane));
            float2 f2 = __half22float2(__ldg(hp + 2*32 + lane));
            float2 f3 = __half22float2(__ldg(hp + 3*32 + lane));
            acc.x += g.x*f0.x + g.y*f1.x + g.z*f2.x + g.w*f3.x;
            acc.y += g.x*f0.y + g.y*f1.y + g.z*f2.y + g.w*f3.y;
        }
    }
    for (; i < end; i++) {
        int    s = __ldg(g_rsrc + i);
        float4 g = __ldg(g_rg   + i);
        const __half2* hp = reinterpret_cast<const __half2*>(g_h + (size_t)s * KH);
        float2 f0 = __half22float2(__ldg(hp + 0*32 + lane));
        float2 f1 = __half22float2(__ldg(hp + 1*32 + lane));
        float2 f2 = __half22float2(__ldg(hp + 2*32 + lane));
        float2 f3 = __half22float2(__ldg(hp + 3*32 + lane));
        acc.x += g.x*f0.x + g.y*f1.x + g.z*f2.x + g.w*f3.x;
        acc.y += g.x*f0.y + g.y*f1.y + g.z*f2.y + g.w*f3.y;
    }

    *reinterpret_cast<float2*>(out + (size_t)v * OUT_FEATS + lane * 2) = acc;
}

// ---------------------------------------------------------------------------
// Launch
// ---------------------------------------------------------------------------
extern "C" void kernel_launch(void* const* d_in, const int* in_sizes, int n_in,
                              void* d_out, int out_size) {
    const float* feat      = (const float*)d_in[0];   // [N, 64]
    const float* pseudo    = (const float*)d_in[1];   // [E, 3]
    const int*   src       = (const int*)  d_in[2];   // [E]
    const int*   dst       = (const int*)  d_in[3];   // [E]
    const float* W_fc      = (const float*)d_in[4];   // [256, 64]
    const float* mu        = (const float*)d_in[5];   // [4, 3]
    const float* inv_sigma = (const float*)d_in[6];   // [4, 3]
    const float* bias      = (const float*)d_in[7];   // [64]
    float* out = (float*)d_out;                       // [N, 64]

    // CSR build (by dst)
    zero_count_kernel<<<(N_NODES + 255) / 256, 256>>>();
    hist_kernel<<<(N_EDGES + 255) / 256, 256>>>(dst);
    scan1_kernel<<<NBLK_SCAN, SCAN_BLOCK>>>();
    scan2_kernel<<<1, 256>>>();
    scan3_kernel<<<NBLK_SCAN, SCAN_BLOCK>>>();

    // Node projections (independent of CSR build)
    proj_kernel<<<(N_NODES + PROJ_TILE - 1) / PROJ_TILE, 256>>>(feat, W_fc);

    // Bin edges with precomputed gaussian weights
    bin_kernel<<<(N_EDGES + 255) / 256, 256>>>(pseudo, src, dst, mu, inv_sigma);

    // Atomic-free aggregation + residual + bias
    agg_kernel<<<(N_NODES + AGG_WARPS - 1) / AGG_WARPS, AGG_WARPS * 32>>>(feat, bias, out);
}